// round 7
// baseline (speedup 1.0000x reference)
#include <cuda_runtime.h>
#include <cuda_bf16.h>

// ---------------------------------------------------------------------------
// Cl(4,1) CGA sandwich:  out = decode( (M P) ~M ),  M even versor, P grade-1.
// One point per thread (best measured structure), streaming cache hints
// (__ldcs / __stcs) since there is zero data reuse.
// Blade structure via constexpr functions + template recursion -> all indices
// are compile-time literals -> straight-line FFMA on registers.
// ---------------------------------------------------------------------------

namespace cga {

__host__ __device__ constexpr int popc5(int x) {
    int c = 0;
    for (int i = 0; i < 5; i++) c += (x >> i) & 1;
    return c;
}

__host__ __device__ constexpr int even_blade(int i) {
    constexpr int E[16] = {0,3,5,6,9,10,12,15,17,18,20,23,24,27,29,30};
    return E[i];
}
__host__ __device__ constexpr int odd_blade(int i) {
    constexpr int O[16] = {1,2,4,7,8,11,13,14,16,19,21,22,25,26,28,31};
    return O[i];
}
__host__ __device__ constexpr int g1_blade(int i) {
    constexpr int G[5] = {1,2,4,8,16};
    return G[i];
}
__host__ __device__ constexpr int even_index_of(int b) {
    for (int i = 0; i < 16; i++) if (even_blade(i) == b) return i;
    return -1;
}
__host__ __device__ constexpr int odd_index_of(int b) {
    for (int i = 0; i < 16; i++) if (odd_blade(i) == b) return i;
    return -1;
}

__host__ __device__ constexpr float blade_sign(int a, int b) {
    int s = 0;
    for (int t = a >> 1; t; t >>= 1) s += popc5(t & b);
    float sign = (s & 1) ? -1.0f : 1.0f;
    if ((a & b) & 16) sign = -sign;   // e5 squares to -1
    return sign;
}

__host__ __device__ constexpr float rev_sign(int b) {
    int g = popc5(b);
    return ((g * (g - 1) / 2) & 1) ? -1.0f : 1.0f;
}

__host__ __device__ constexpr int   mx_ie (int io, int ip) { return even_index_of(odd_blade(io) ^ g1_blade(ip)); }
__host__ __device__ constexpr float mx_sgn(int io, int ip) { return blade_sign(odd_blade(io) ^ g1_blade(ip), g1_blade(ip)); }
__host__ __device__ constexpr int   q_io (int iq, int ie) { return odd_index_of(g1_blade(iq) ^ even_blade(ie)); }
__host__ __device__ constexpr float q_sgn(int iq, int ie) {
    return blade_sign(g1_blade(iq) ^ even_blade(ie), even_blade(ie)) * rev_sign(even_blade(ie));
}

// ---- template-recursive unrollers ----

template<int IO, int IP>
struct MxTerm {
    static __device__ __forceinline__ float run(const float (&v)[16], const float (&p)[5]) {
        float prev = MxTerm<IO, IP - 1>::run(v, p);
        constexpr int   ie = mx_ie(IO, IP);
        constexpr float s  = mx_sgn(IO, IP);
        return (s > 0.0f) ? fmaf(v[ie], p[IP], prev) : fmaf(-v[ie], p[IP], prev);
    }
};
template<int IO>
struct MxTerm<IO, -1> {
    static __device__ __forceinline__ float run(const float (&)[16], const float (&)[5]) { return 0.0f; }
};

template<int IO>
struct MxAll {
    static __device__ __forceinline__ void run(float (&mx)[16], const float (&v)[16], const float (&p)[5]) {
        MxAll<IO - 1>::run(mx, v, p);
        mx[IO] = MxTerm<IO, 4>::run(v, p);
    }
};
template<>
struct MxAll<-1> {
    static __device__ __forceinline__ void run(float (&)[16], const float (&)[16], const float (&)[5]) {}
};

template<int IQ, int IE>
struct QTerm {
    static __device__ __forceinline__ float run(const float (&mx)[16], const float (&v)[16]) {
        float prev = QTerm<IQ, IE - 1>::run(mx, v);
        constexpr int   io = q_io(IQ, IE);
        constexpr float s  = q_sgn(IQ, IE);
        return (s > 0.0f) ? fmaf(mx[io], v[IE], prev) : fmaf(-mx[io], v[IE], prev);
    }
};
template<int IQ>
struct QTerm<IQ, -1> {
    static __device__ __forceinline__ float run(const float (&)[16], const float (&)[16]) { return 0.0f; }
};

template<int IQ>
struct QAll {
    static __device__ __forceinline__ void run(float (&q)[5], const float (&mx)[16], const float (&v)[16]) {
        QAll<IQ - 1>::run(q, mx, v);
        q[IQ] = QTerm<IQ, 15>::run(mx, v);
    }
};
template<>
struct QAll<-1> {
    static __device__ __forceinline__ void run(float (&)[5], const float (&)[16], const float (&)[16]) {}
};

} // namespace cga

__global__ __launch_bounds__(256)
void cga_sandwich_kernel(const float* __restrict__ versor,
                         const float* __restrict__ x,
                         float* __restrict__ out,
                         int n)
{
    int i = blockIdx.x * blockDim.x + threadIdx.x;
    if (i >= n) return;

    // ---- load versor: 4x LDG.128 streaming (evict-first) ----
    float v[16];
    const float4* v4 = reinterpret_cast<const float4*>(versor + (size_t)i * 16);
    #pragma unroll
    for (int j = 0; j < 4; j++) {
        float4 t = __ldcs(v4 + j);
        v[4*j+0] = t.x; v[4*j+1] = t.y; v[4*j+2] = t.z; v[4*j+3] = t.w;
    }

    // ---- load point (streaming) + CGA encode ----
    const float* xp = x + (size_t)i * 3;
    float x0 = __ldcs(xp + 0);
    float x1 = __ldcs(xp + 1);
    float x2 = __ldcs(xp + 2);
    float hs = 0.5f * (x0*x0 + x1*x1 + x2*x2);
    float p[5] = { x0, x1, x2, hs - 0.5f, hs + 0.5f };

    // ---- mx = M * P  (16 odd comps, 5 terms each) ----
    float mx[16];
    cga::MxAll<15>::run(mx, v, p);

    // ---- q = (M P) ~M, grade-1 part (5 comps, 16 terms each) ----
    float q[5];
    cga::QAll<4>::run(q, mx, v);

    // ---- decode: scale = q[e5] - q[e4]; out = q_xyz / scale ----
    float s = q[4] - q[3];
    float inv = __frcp_rn(s);
    inv = inv * (2.0f - s * inv);   // one Newton step

    float* op = out + (size_t)i * 3;
    __stcs(op + 0, q[0] * inv);
    __stcs(op + 1, q[1] * inv);
    __stcs(op + 2, q[2] * inv);
}

extern "C" void kernel_launch(void* const* d_in, const int* in_sizes, int n_in,
                              void* d_out, int out_size)
{
    const float* versor = (const float*)d_in[0];   // (N, 16) f32
    const float* x      = (const float*)d_in[1];   // (N, 3)  f32
    float* out          = (float*)d_out;           // (N, 3)  f32

    int n = in_sizes[0] / 16;
    int threads = 256;
    int blocks = (n + threads - 1) / threads;
    cga_sandwich_kernel<<<blocks, threads>>>(versor, x, out, n);
}

// round 8
// speedup vs baseline: 1.1222x; 1.1222x over previous
#include <cuda_runtime.h>
#include <cuda_bf16.h>

// ---------------------------------------------------------------------------
// Cl(4,1) CGA sandwich:  out = decode( (M P) ~M ),  M even versor, P grade-1.
// One point per thread; x and out staged through shared memory so ALL global
// traffic for them is 128-bit (full-sector stores, 3x fewer L1 wavefronts).
// Versor path stays 4x LDG.128 direct. Default cache policy (evict-normal):
// .cs hints measured as a hard regression (partial-sector writebacks).
// ---------------------------------------------------------------------------

namespace cga {

__host__ __device__ constexpr int popc5(int x) {
    int c = 0;
    for (int i = 0; i < 5; i++) c += (x >> i) & 1;
    return c;
}

__host__ __device__ constexpr int even_blade(int i) {
    constexpr int E[16] = {0,3,5,6,9,10,12,15,17,18,20,23,24,27,29,30};
    return E[i];
}
__host__ __device__ constexpr int odd_blade(int i) {
    constexpr int O[16] = {1,2,4,7,8,11,13,14,16,19,21,22,25,26,28,31};
    return O[i];
}
__host__ __device__ constexpr int g1_blade(int i) {
    constexpr int G[5] = {1,2,4,8,16};
    return G[i];
}
__host__ __device__ constexpr int even_index_of(int b) {
    for (int i = 0; i < 16; i++) if (even_blade(i) == b) return i;
    return -1;
}
__host__ __device__ constexpr int odd_index_of(int b) {
    for (int i = 0; i < 16; i++) if (odd_blade(i) == b) return i;
    return -1;
}

__host__ __device__ constexpr float blade_sign(int a, int b) {
    int s = 0;
    for (int t = a >> 1; t; t >>= 1) s += popc5(t & b);
    float sign = (s & 1) ? -1.0f : 1.0f;
    if ((a & b) & 16) sign = -sign;   // e5 squares to -1
    return sign;
}

__host__ __device__ constexpr float rev_sign(int b) {
    int g = popc5(b);
    return ((g * (g - 1) / 2) & 1) ? -1.0f : 1.0f;
}

__host__ __device__ constexpr int   mx_ie (int io, int ip) { return even_index_of(odd_blade(io) ^ g1_blade(ip)); }
__host__ __device__ constexpr float mx_sgn(int io, int ip) { return blade_sign(odd_blade(io) ^ g1_blade(ip), g1_blade(ip)); }
__host__ __device__ constexpr int   q_io (int iq, int ie) { return odd_index_of(g1_blade(iq) ^ even_blade(ie)); }
__host__ __device__ constexpr float q_sgn(int iq, int ie) {
    return blade_sign(g1_blade(iq) ^ even_blade(ie), even_blade(ie)) * rev_sign(even_blade(ie));
}

// ---- template-recursive unrollers ----

template<int IO, int IP>
struct MxTerm {
    static __device__ __forceinline__ float run(const float (&v)[16], const float (&p)[5]) {
        float prev = MxTerm<IO, IP - 1>::run(v, p);
        constexpr int   ie = mx_ie(IO, IP);
        constexpr float s  = mx_sgn(IO, IP);
        return (s > 0.0f) ? fmaf(v[ie], p[IP], prev) : fmaf(-v[ie], p[IP], prev);
    }
};
template<int IO>
struct MxTerm<IO, -1> {
    static __device__ __forceinline__ float run(const float (&)[16], const float (&)[5]) { return 0.0f; }
};

template<int IO>
struct MxAll {
    static __device__ __forceinline__ void run(float (&mx)[16], const float (&v)[16], const float (&p)[5]) {
        MxAll<IO - 1>::run(mx, v, p);
        mx[IO] = MxTerm<IO, 4>::run(v, p);
    }
};
template<>
struct MxAll<-1> {
    static __device__ __forceinline__ void run(float (&)[16], const float (&)[16], const float (&)[5]) {}
};

template<int IQ, int IE>
struct QTerm {
    static __device__ __forceinline__ float run(const float (&mx)[16], const float (&v)[16]) {
        float prev = QTerm<IQ, IE - 1>::run(mx, v);
        constexpr int   io = q_io(IQ, IE);
        constexpr float s  = q_sgn(IQ, IE);
        return (s > 0.0f) ? fmaf(mx[io], v[IE], prev) : fmaf(-mx[io], v[IE], prev);
    }
};
template<int IQ>
struct QTerm<IQ, -1> {
    static __device__ __forceinline__ float run(const float (&)[16], const float (&)[16]) { return 0.0f; }
};

template<int IQ>
struct QAll {
    static __device__ __forceinline__ void run(float (&q)[5], const float (&mx)[16], const float (&v)[16]) {
        QAll<IQ - 1>::run(q, mx, v);
        q[IQ] = QTerm<IQ, 15>::run(mx, v);
    }
};
template<>
struct QAll<-1> {
    static __device__ __forceinline__ void run(float (&)[5], const float (&)[16], const float (&)[16]) {}
};

// core math: p(5) -> out(3) given versor regs
__device__ __forceinline__ void sandwich_core(const float (&v)[16],
                                              float x0, float x1, float x2,
                                              float (&o)[3])
{
    float hs = 0.5f * (x0*x0 + x1*x1 + x2*x2);
    float p[5] = { x0, x1, x2, hs - 0.5f, hs + 0.5f };

    float mx[16];
    MxAll<15>::run(mx, v, p);

    float q[5];
    QAll<4>::run(q, mx, v);

    float s = q[4] - q[3];
    float inv = __frcp_rn(s);
    inv = inv * (2.0f - s * inv);   // Newton step
    o[0] = q[0] * inv;
    o[1] = q[1] * inv;
    o[2] = q[2] * inv;
}

} // namespace cga

constexpr int BLK = 256;

__global__ __launch_bounds__(BLK)
void cga_sandwich_kernel(const float* __restrict__ versor,
                         const float* __restrict__ x,
                         float* __restrict__ out,
                         int n)
{
    __shared__ float sx[BLK * 3];   // 3 KB staging for x, reused for out

    int tid  = threadIdx.x;
    int base = blockIdx.x * BLK;    // first point of this block
    int i    = base + tid;

    bool full_block = (base + BLK <= n);

    // ---- stage x into smem: 192 x LDG.128 covering 768 floats ----
    if (full_block) {
        if (tid < (BLK * 3) / 4) {
            const float4* xs4 = reinterpret_cast<const float4*>(x + (size_t)base * 3);
            float4 t = xs4[tid];
            float4* s4 = reinterpret_cast<float4*>(sx);
            s4[tid] = t;
        }
    } else if (i < n) {
        // tail block: scalar staging
        const float* xp = x + (size_t)i * 3;
        sx[3*tid+0] = xp[0];
        sx[3*tid+1] = xp[1];
        sx[3*tid+2] = xp[2];
    }

    // ---- load versor: 4x LDG.128 direct (dense, default policy) ----
    float v[16];
    if (i < n) {
        const float4* v4 = reinterpret_cast<const float4*>(versor + (size_t)i * 16);
        #pragma unroll
        for (int j = 0; j < 4; j++) {
            float4 t = v4[j];
            v[4*j+0] = t.x; v[4*j+1] = t.y; v[4*j+2] = t.z; v[4*j+3] = t.w;
        }
    }

    __syncthreads();   // x staging visible

    // ---- compute; read own 3 floats (conflict-free: stride 3, gcd(3,32)=1) ----
    float o[3] = {0.f, 0.f, 0.f};
    if (i < n) {
        float x0 = sx[3*tid+0];
        float x1 = sx[3*tid+1];
        float x2 = sx[3*tid+2];
        cga::sandwich_core(v, x0, x1, x2, o);
    }

    // write own 3 outputs back to the SAME smem slots (no cross-thread hazard:
    // element 3t+c is read and written only by thread t)
    sx[3*tid+0] = o[0];
    sx[3*tid+1] = o[1];
    sx[3*tid+2] = o[2];

    __syncthreads();   // out staging complete

    // ---- drain out: 192 x STG.128 (full sectors at issue) ----
    if (full_block) {
        if (tid < (BLK * 3) / 4) {
            const float4* s4 = reinterpret_cast<const float4*>(sx);
            float4 t = s4[tid];
            float4* o4 = reinterpret_cast<float4*>(out + (size_t)base * 3);
            o4[tid] = t;
        }
    } else if (i < n) {
        float* op = out + (size_t)i * 3;
        op[0] = sx[3*tid+0];
        op[1] = sx[3*tid+1];
        op[2] = sx[3*tid+2];
    }
}

extern "C" void kernel_launch(void* const* d_in, const int* in_sizes, int n_in,
                              void* d_out, int out_size)
{
    const float* versor = (const float*)d_in[0];   // (N, 16) f32
    const float* x      = (const float*)d_in[1];   // (N, 3)  f32
    float* out          = (float*)d_out;           // (N, 3)  f32

    int n = in_sizes[0] / 16;
    int blocks = (n + BLK - 1) / BLK;
    cga_sandwich_kernel<<<blocks, BLK>>>(versor, x, out, n);
}